// round 11
// baseline (speedup 1.0000x reference)
#include <cuda_runtime.h>
#include <cuda_bf16.h>
#include <cstdint>
#include <cstddef>

// Problem constants
#define B_   64
#define S_   1024
#define CIN_ 256
#define H_   512
#define R4H_ 2048   // 4*H
#define KTOT 768    // CIN + H

// ---------------- device scratch (static globals; no allocation) ----------------
__device__ float g_Wx[R4H_ * CIN_];                       // 2 MB   packed Wx[r][k]
__device__ float g_Wh[R4H_ * H_];                         // 4 MB   packed Wh[r][k]
__device__ float g_Xpre[(size_t)S_ * R4H_ * B_];          // 512 MB Xpre[t][r][b]
__device__ float g_h[2][B_ * H_];                         // h ping-pong  [b][j]
__device__ unsigned g_flags[128];                         // grid barrier flags (monotonic)

// packed f32x2 FMA: acc += a * b  (elementwise on packed pairs)
#define FMA2(acc, a, b) \
    asm("fma.rn.f32x2 %0, %1, %2, %0;" : "+l"(acc) : "l"(a), "l"(b))

__device__ __forceinline__ void unpack2(unsigned long long v, float& lo, float& hi) {
    asm("mov.b64 {%0, %1}, %2;" : "=f"(lo), "=f"(hi) : "l"(v));
}

__device__ __forceinline__ float sigf(float x) {
    return 1.0f / (1.0f + __expf(-x));
}

__device__ __forceinline__ void cp_async16(float* dst_smem, const float* src_glob) {
    unsigned ds = (unsigned)__cvta_generic_to_shared(dst_smem);
    asm volatile("cp.async.cg.shared.global [%0], [%1], 16;"
                 :: "r"(ds), "l"(src_glob) : "memory");
}
#define CP_COMMIT() asm volatile("cp.async.commit_group;" ::: "memory")
#define CP_WAIT(n)  asm volatile("cp.async.wait_group %0;" :: "n"(n) : "memory")
#define NBAR(id, cnt) asm volatile("bar.sync %0, %1;" :: "r"(id), "r"(cnt) : "memory")

// ---------------- kernel 1: repack W center tap ----------------
__global__ void repack_kernel(const float* __restrict__ W) {
    int idx = blockIdx.x * 256 + threadIdx.x;   // 0 .. 2048*768-1
    if (idx < R4H_ * KTOT) {
        int r = idx / KTOT;
        int k = idx % KTOT;
        float v = W[(size_t)idx * 3 + 1];       // W[r][k][1]
        if (k < CIN_) g_Wx[r * CIN_ + k] = v;
        else          g_Wh[r * H_ + (k - CIN_)] = v;
    }
}

// ---------------- kernel 2: Xpre[t][r][b] = sum_k Wx[r][k] * x[b][t][k] ----------------
#define XP_SMEM ((128 * 68 + 64 * 68) * 4)

__global__ void __launch_bounds__(256, 2) xproj_kernel(const float* __restrict__ x) {
    extern __shared__ float sm1[];
    float* Wx_s = sm1;              // [128][68]
    float* x_s  = sm1 + 128 * 68;   // [64][68]

    const int t   = blockIdx.y;
    const int rt  = blockIdx.x;
    const int tid = threadIdx.x;
    const int rowpos = tid >> 4;    // 0..15
    const int bpos   = tid & 15;    // 0..15

    unsigned long long acc[8][4];
#pragma unroll
    for (int i = 0; i < 8; i++)
#pragma unroll
        for (int j = 0; j < 4; j++) acc[i][j] = 0ull;

    for (int kc = 0; kc < CIN_; kc += 64) {
        __syncthreads();
#pragma unroll
        for (int i = 0; i < 8; i++) {
            int id = tid + i * 256;
            int r  = id >> 4;
            int kq = (id & 15) << 2;
            float4 v = *(const float4*)(g_Wx + (size_t)(rt * 128 + r) * CIN_ + kc + kq);
            *(float4*)(Wx_s + r * 68 + kq) = v;
        }
#pragma unroll
        for (int i = 0; i < 4; i++) {
            int id = tid + i * 256;
            int b  = id >> 4;
            int kq = (id & 15) << 2;
            float4 v = *(const float4*)(x + (size_t)b * (S_ * CIN_) + (size_t)t * CIN_ + kc + kq);
            *(float4*)(x_s + b * 68 + kq) = v;
        }
        __syncthreads();

#pragma unroll 4
        for (int kk = 0; kk < 64; kk += 2) {
            unsigned long long wv[8], xv[4];
#pragma unroll
            for (int i = 0; i < 8; i++)
                wv[i] = *(const unsigned long long*)(Wx_s + (i * 16 + rowpos) * 68 + kk);
#pragma unroll
            for (int j = 0; j < 4; j++)
                xv[j] = *(const unsigned long long*)(x_s + (j * 16 + bpos) * 68 + kk);
#pragma unroll
            for (int i = 0; i < 8; i++)
#pragma unroll
                for (int j = 0; j < 4; j++)
                    FMA2(acc[i][j], wv[i], xv[j]);
        }
    }

    const size_t obase = (size_t)t * R4H_ * B_;
#pragma unroll
    for (int i = 0; i < 8; i++) {
        int r = rt * 128 + i * 16 + rowpos;
#pragma unroll
        for (int j = 0; j < 4; j++) {
            int b = j * 16 + bpos;
            float lo, hi;
            unpack2(acc[i][j], lo, hi);
            g_Xpre[obase + (size_t)r * B_ + b] = lo + hi;
        }
    }
}

// ---------------- kernel 3: persistent recurrent LSTM (pipelined) ----------------
// grid = 128 CTAs, 256 threads. CTA g owns hidden units [4g,4g+4) => 16 gate rows.
// K-group grp (64 threads) owns K chunk [grp*128, grp*128+128): it polls ONLY the
// 32 CTAs producing that chunk, cp.async-stages it in two halves, and GEMMs each
// half as it lands (named barriers, no CTA-wide sync until the partial reduce).
#define ST_SMEM ((16 * 516 + 64 * 516 + 4 * 16 * 68) * 4)

__global__ void __launch_bounds__(256, 1) lstm_step_kernel(
    const float* __restrict__ h0, const float* __restrict__ c0,
    const float* __restrict__ bias, float* __restrict__ out)
{
    extern __shared__ float sm2[];
    float* wh_s = sm2;                        // [16][516]
    float* h_s  = sm2 + 16 * 516;             // [64][516]
    float* part = sm2 + 16 * 516 + 64 * 516;  // [4 grp][16 row][68]

    const int g   = blockIdx.x;
    const int tid = threadIdx.x;

    // GEMM role
    const int grp    = tid >> 6;        // K group 0..3, chunk [grp*128, grp*128+128)
    const int lt     = tid & 63;
    const int rowpos = lt >> 4;         // gate q = rowpos (0..3)
    const int bpos   = lt & 15;
    const int kbase  = grp * 128;

    // elementwise role
    const int eb    = tid >> 2;         // batch 0..63
    const int ejl   = tid & 3;          // hidden-local 0..3
    const int jglob = g * 4 + ejl;

    // load Wh slice into smem: local row lr = q*4 + jl
#pragma unroll
    for (int i = 0; i < 8; i++) {
        int id = tid + i * 256;          // 0..2047
        int lr = id >> 7;                // 0..15
        int kq = (id & 127) << 2;        // 0..508
        int q  = lr >> 2, jl = lr & 3;
        int gr = q * H_ + g * 4 + jl;
        float4 v = *(const float4*)(g_Wh + (size_t)gr * H_ + kq);
        *(float4*)(wh_s + lr * 516 + kq) = v;
    }

    float creg = c0[eb * H_ + jglob];
    float bi0 = bias[0 * H_ + jglob];
    float bi1 = bias[1 * H_ + jglob];
    float bi2 = bias[2 * H_ + jglob];
    float bi3 = bias[3 * H_ + jglob];

    unsigned base;
    asm volatile("ld.global.acquire.gpu.b32 %0, [%1];" : "=r"(base) : "l"(g_flags + g) : "memory");

    __syncthreads();

    for (int t = 0; t < S_; ++t) {
        // prefetch Xpre for elementwise (independent; overlaps the poll)
        const float* xp = g_Xpre + ((size_t)t * R4H_ + jglob) * B_ + eb;
        float xv0 = xp[0];
        float xv1 = xp[(size_t)1 * H_ * B_];
        float xv2 = xp[(size_t)2 * H_ * B_];
        float xv3 = xp[(size_t)3 * H_ * B_];

        const float* hsrc = (t == 0) ? h0 : g_h[(t - 1) & 1];

        // group-partitioned poll: chunk grp is produced by CTAs [grp*32, grp*32+32)
        if (t > 0) {
            if (lt < 32) {
                const unsigned* fp = g_flags + grp * 32 + lt;
                unsigned tgt = base + (unsigned)t;
                unsigned v;
                int spins = 0;
                while (1) {
                    asm volatile("ld.global.acquire.gpu.b32 %0, [%1];"
                                 : "=r"(v) : "l"(fp) : "memory");
                    if ((int)(v - tgt) >= 0) break;
                    if (++spins > 4) __nanosleep(32);
                }
            }
            NBAR(1 + grp, 64);
        }

        // stage this group's chunk in two 64-wide K halves via cp.async
#pragma unroll
        for (int half = 0; half < 2; half++) {
#pragma unroll
            for (int i = 0; i < 16; i++) {
                int id = lt + i * 64;               // 0..1023
                int b  = id >> 4;                   // 0..63
                int kq = ((id & 15) << 2) + half * 64;
                cp_async16(h_s + b * 516 + kbase + kq,
                           hsrc + b * H_ + kbase + kq);
            }
            CP_COMMIT();
        }

        // GEMM with half-pipelining
        unsigned long long acc[4][4];
#pragma unroll
        for (int i = 0; i < 4; i++)
#pragma unroll
            for (int j = 0; j < 4; j++) acc[i][j] = 0ull;

        CP_WAIT(1);
        NBAR(1 + grp, 64);
#pragma unroll 4
        for (int kk = 0; kk < 64; kk += 4) {
            int k = kbase + kk;
            ulonglong2 wv[4], hv[4];
#pragma unroll
            for (int i = 0; i < 4; i++)
                wv[i] = *(const ulonglong2*)(wh_s + (rowpos * 4 + i) * 516 + k);
#pragma unroll
            for (int j = 0; j < 4; j++)
                hv[j] = *(const ulonglong2*)(h_s + (j * 16 + bpos) * 516 + k);
#pragma unroll
            for (int i = 0; i < 4; i++)
#pragma unroll
                for (int j = 0; j < 4; j++) {
                    FMA2(acc[i][j], wv[i].x, hv[j].x);
                    FMA2(acc[i][j], wv[i].y, hv[j].y);
                }
        }
        CP_WAIT(0);
        NBAR(1 + grp, 64);
#pragma unroll 4
        for (int kk = 64; kk < 128; kk += 4) {
            int k = kbase + kk;
            ulonglong2 wv[4], hv[4];
#pragma unroll
            for (int i = 0; i < 4; i++)
                wv[i] = *(const ulonglong2*)(wh_s + (rowpos * 4 + i) * 516 + k);
#pragma unroll
            for (int j = 0; j < 4; j++)
                hv[j] = *(const ulonglong2*)(h_s + (j * 16 + bpos) * 516 + k);
#pragma unroll
            for (int i = 0; i < 4; i++)
#pragma unroll
                for (int j = 0; j < 4; j++) {
                    FMA2(acc[i][j], wv[i].x, hv[j].x);
                    FMA2(acc[i][j], wv[i].y, hv[j].y);
                }
        }

        // write partials: part[grp][rowpos*4+i][j*16+bpos]
#pragma unroll
        for (int i = 0; i < 4; i++)
#pragma unroll
            for (int j = 0; j < 4; j++) {
                float lo, hi;
                unpack2(acc[i][j], lo, hi);
                part[grp * 1088 + (rowpos * 4 + i) * 68 + (j * 16 + bpos)] = lo + hi;
            }
        __syncthreads();

        // elementwise: this thread owns (batch eb, hidden jglob)
        float gate0 = bi0 + xv0, gate1 = bi1 + xv1, gate2 = bi2 + xv2, gate3 = bi3 + xv3;
#pragma unroll
        for (int gr2 = 0; gr2 < 4; gr2++) {
            const float* p = part + gr2 * 1088;
            gate0 += p[(0 * 4 + ejl) * 68 + eb];
            gate1 += p[(1 * 4 + ejl) * 68 + eb];
            gate2 += p[(2 * 4 + ejl) * 68 + eb];
            gate3 += p[(3 * 4 + ejl) * 68 + eb];
        }
        float ig = sigf(gate0);
        float fg = sigf(gate1);
        float gg = tanhf(gate2);
        float og = sigf(gate3);
        creg = fg * creg + ig * gg;
        float hnew = og * tanhf(creg);

        if (t == S_ - 1) {
            out[((size_t)eb * S_ + t) * H_ + jglob] = hnew;
            out[(size_t)B_ * S_ * H_ + eb * H_ + jglob] = hnew;                 // final h
            out[(size_t)B_ * S_ * H_ + B_ * H_ + eb * H_ + jglob] = creg;       // final c
        } else {
            g_h[t & 1][eb * H_ + jglob] = hnew;
            __syncthreads();   // all h stores of this CTA issued
            // release: st.release orders the prior weak h-stores at gpu scope
            if (tid == 0) {
                unsigned tgt = base + (unsigned)t + 1u;
                asm volatile("st.global.release.gpu.b32 [%0], %1;"
                             :: "l"(g_flags + g), "r"(tgt) : "memory");
            }
            // out store off the critical path, after the release
            out[((size_t)eb * S_ + t) * H_ + jglob] = hnew;
        }
    }
}

// ---------------- launch ----------------
extern "C" void kernel_launch(void* const* d_in, const int* in_sizes, int n_in,
                              void* d_out, int out_size) {
    (void)in_sizes; (void)n_in; (void)out_size;
    const float* x  = (const float*)d_in[0];
    const float* W  = (const float*)d_in[1];
    const float* bb = (const float*)d_in[2];
    const float* h0 = (const float*)d_in[3];
    const float* c0 = (const float*)d_in[4];
    float* out = (float*)d_out;

    repack_kernel<<<(R4H_ * KTOT + 255) / 256, 256>>>(W);

    cudaFuncSetAttribute(xproj_kernel, cudaFuncAttributeMaxDynamicSharedMemorySize, XP_SMEM);
    xproj_kernel<<<dim3(16, S_), 256, XP_SMEM>>>(x);

    cudaFuncSetAttribute(lstm_step_kernel, cudaFuncAttributeMaxDynamicSharedMemorySize, ST_SMEM);
    lstm_step_kernel<<<128, 256, ST_SMEM>>>(h0, c0, bb, out);
}

// round 12
// speedup vs baseline: 1.1404x; 1.1404x over previous
#include <cuda_runtime.h>
#include <cuda_bf16.h>
#include <cstdint>
#include <cstddef>

// Problem constants
#define B_   64
#define S_   1024
#define CIN_ 256
#define H_   512
#define R4H_ 2048   // 4*H
#define KTOT 768    // CIN + H

// ---------------- device scratch (static globals; no allocation) ----------------
__device__ float g_Wx[R4H_ * CIN_];                       // 2 MB   packed Wx[r][k]
__device__ float g_Wh[R4H_ * H_];                         // 4 MB   packed Wh[r][k]
__device__ float g_Xpre[(size_t)S_ * R4H_ * B_];          // 512 MB Xpre[t][r][b]
__device__ float g_h[2][B_ * H_];                         // h ping-pong  [b][j]
__device__ unsigned g_flags[128];                         // grid barrier flags (monotonic)

// packed f32x2 FMA: acc += a * b  (elementwise on packed pairs)
#define FMA2(acc, a, b) \
    asm("fma.rn.f32x2 %0, %1, %2, %0;" : "+l"(acc) : "l"(a), "l"(b))

__device__ __forceinline__ void unpack2(unsigned long long v, float& lo, float& hi) {
    asm("mov.b64 {%0, %1}, %2;" : "=f"(lo), "=f"(hi) : "l"(v));
}

__device__ __forceinline__ float sigf(float x) {
    return 1.0f / (1.0f + __expf(-x));
}

__device__ __forceinline__ void cp_async16(float* dst_smem, const float* src_glob) {
    unsigned ds = (unsigned)__cvta_generic_to_shared(dst_smem);
    asm volatile("cp.async.cg.shared.global [%0], [%1], 16;"
                 :: "r"(ds), "l"(src_glob) : "memory");
}
#define CP_COMMIT() asm volatile("cp.async.commit_group;" ::: "memory")
#define CP_WAIT(n)  asm volatile("cp.async.wait_group %0;" :: "n"(n) : "memory")
#define NBAR(id, cnt) asm volatile("bar.sync %0, %1;" :: "r"(id), "r"(cnt) : "memory")

// ---------------- kernel 1: repack W center tap ----------------
__global__ void repack_kernel(const float* __restrict__ W) {
    int idx = blockIdx.x * 256 + threadIdx.x;   // 0 .. 2048*768-1
    if (idx < R4H_ * KTOT) {
        int r = idx / KTOT;
        int k = idx % KTOT;
        float v = W[(size_t)idx * 3 + 1];       // W[r][k][1]
        if (k < CIN_) g_Wx[r * CIN_ + k] = v;
        else          g_Wh[r * H_ + (k - CIN_)] = v;
    }
}

// ---------------- kernel 2: Xpre[t][r][b] = sum_k Wx[r][k] * x[b][t][k] ----------------
#define XP_SMEM ((128 * 68 + 64 * 68) * 4)

__global__ void __launch_bounds__(256, 2) xproj_kernel(const float* __restrict__ x) {
    extern __shared__ float sm1[];
    float* Wx_s = sm1;              // [128][68]
    float* x_s  = sm1 + 128 * 68;   // [64][68]

    const int t   = blockIdx.y;
    const int rt  = blockIdx.x;
    const int tid = threadIdx.x;
    const int rowpos = tid >> 4;    // 0..15
    const int bpos   = tid & 15;    // 0..15

    unsigned long long acc[8][4];
#pragma unroll
    for (int i = 0; i < 8; i++)
#pragma unroll
        for (int j = 0; j < 4; j++) acc[i][j] = 0ull;

    for (int kc = 0; kc < CIN_; kc += 64) {
        __syncthreads();
#pragma unroll
        for (int i = 0; i < 8; i++) {
            int id = tid + i * 256;
            int r  = id >> 4;
            int kq = (id & 15) << 2;
            float4 v = *(const float4*)(g_Wx + (size_t)(rt * 128 + r) * CIN_ + kc + kq);
            *(float4*)(Wx_s + r * 68 + kq) = v;
        }
#pragma unroll
        for (int i = 0; i < 4; i++) {
            int id = tid + i * 256;
            int b  = id >> 4;
            int kq = (id & 15) << 2;
            float4 v = *(const float4*)(x + (size_t)b * (S_ * CIN_) + (size_t)t * CIN_ + kc + kq);
            *(float4*)(x_s + b * 68 + kq) = v;
        }
        __syncthreads();

#pragma unroll 4
        for (int kk = 0; kk < 64; kk += 2) {
            unsigned long long wv[8], xv[4];
#pragma unroll
            for (int i = 0; i < 8; i++)
                wv[i] = *(const unsigned long long*)(Wx_s + (i * 16 + rowpos) * 68 + kk);
#pragma unroll
            for (int j = 0; j < 4; j++)
                xv[j] = *(const unsigned long long*)(x_s + (j * 16 + bpos) * 68 + kk);
#pragma unroll
            for (int i = 0; i < 8; i++)
#pragma unroll
                for (int j = 0; j < 4; j++)
                    FMA2(acc[i][j], wv[i], xv[j]);
        }
    }

    const size_t obase = (size_t)t * R4H_ * B_;
#pragma unroll
    for (int i = 0; i < 8; i++) {
        int r = rt * 128 + i * 16 + rowpos;
#pragma unroll
        for (int j = 0; j < 4; j++) {
            int b = j * 16 + bpos;
            float lo, hi;
            unpack2(acc[i][j], lo, hi);
            g_Xpre[obase + (size_t)r * B_ + b] = lo + hi;
        }
    }
}

// ---------------- kernel 3: persistent recurrent LSTM (pipelined) ----------------
// grid = 128 CTAs, 256 threads. CTA g owns hidden units [4g,4g+4) => 16 gate rows.
// K-group grp (64 threads) owns K chunk [grp*128, grp*128+128): it polls ONLY the
// 32 CTAs producing that chunk, cp.async-stages it in two halves, and GEMMs each
// half as it lands (named barriers, no CTA-wide sync until the partial reduce).
#define ST_SMEM ((16 * 516 + 64 * 516 + 4 * 16 * 68) * 4)

__global__ void __launch_bounds__(256, 1) lstm_step_kernel(
    const float* __restrict__ h0, const float* __restrict__ c0,
    const float* __restrict__ bias, float* __restrict__ out)
{
    extern __shared__ float sm2[];
    float* wh_s = sm2;                        // [16][516]
    float* h_s  = sm2 + 16 * 516;             // [64][516]
    float* part = sm2 + 16 * 516 + 64 * 516;  // [4 grp][16 row][68]

    const int g   = blockIdx.x;
    const int tid = threadIdx.x;

    // GEMM role
    const int grp    = tid >> 6;        // K group 0..3, chunk [grp*128, grp*128+128)
    const int lt     = tid & 63;
    const int rowpos = lt >> 4;         // gate q = rowpos (0..3)
    const int bpos   = lt & 15;
    const int kbase  = grp * 128;

    // elementwise role
    const int eb    = tid >> 2;         // batch 0..63
    const int ejl   = tid & 3;          // hidden-local 0..3
    const int jglob = g * 4 + ejl;

    // load Wh slice into smem: local row lr = q*4 + jl
#pragma unroll
    for (int i = 0; i < 8; i++) {
        int id = tid + i * 256;          // 0..2047
        int lr = id >> 7;                // 0..15
        int kq = (id & 127) << 2;        // 0..508
        int q  = lr >> 2, jl = lr & 3;
        int gr = q * H_ + g * 4 + jl;
        float4 v = *(const float4*)(g_Wh + (size_t)gr * H_ + kq);
        *(float4*)(wh_s + lr * 516 + kq) = v;
    }

    float creg = c0[eb * H_ + jglob];
    float bi0 = bias[0 * H_ + jglob];
    float bi1 = bias[1 * H_ + jglob];
    float bi2 = bias[2 * H_ + jglob];
    float bi3 = bias[3 * H_ + jglob];

    unsigned base;
    asm volatile("ld.global.acquire.gpu.b32 %0, [%1];" : "=r"(base) : "l"(g_flags + g) : "memory");

    __syncthreads();

    for (int t = 0; t < S_; ++t) {
        // prefetch Xpre for elementwise (independent; overlaps the poll)
        const float* xp = g_Xpre + ((size_t)t * R4H_ + jglob) * B_ + eb;
        float xv0 = xp[0];
        float xv1 = xp[(size_t)1 * H_ * B_];
        float xv2 = xp[(size_t)2 * H_ * B_];
        float xv3 = xp[(size_t)3 * H_ * B_];

        const float* hsrc = (t == 0) ? h0 : g_h[(t - 1) & 1];

        // group-partitioned poll: chunk grp is produced by CTAs [grp*32, grp*32+32)
        if (t > 0) {
            if (lt < 32) {
                const unsigned* fp = g_flags + grp * 32 + lt;
                unsigned tgt = base + (unsigned)t;
                unsigned v;
                int spins = 0;
                while (1) {
                    asm volatile("ld.global.acquire.gpu.b32 %0, [%1];"
                                 : "=r"(v) : "l"(fp) : "memory");
                    if ((int)(v - tgt) >= 0) break;
                    if (++spins > 4) __nanosleep(32);
                }
            }
            NBAR(1 + grp, 64);
        }

        // stage this group's chunk in two 64-wide K halves via cp.async
#pragma unroll
        for (int half = 0; half < 2; half++) {
#pragma unroll
            for (int i = 0; i < 16; i++) {
                int id = lt + i * 64;               // 0..1023
                int b  = id >> 4;                   // 0..63
                int kq = ((id & 15) << 2) + half * 64;
                cp_async16(h_s + b * 516 + kbase + kq,
                           hsrc + b * H_ + kbase + kq);
            }
            CP_COMMIT();
        }

        // GEMM with half-pipelining
        unsigned long long acc[4][4];
#pragma unroll
        for (int i = 0; i < 4; i++)
#pragma unroll
            for (int j = 0; j < 4; j++) acc[i][j] = 0ull;

        CP_WAIT(1);
        NBAR(1 + grp, 64);
#pragma unroll 4
        for (int kk = 0; kk < 64; kk += 4) {
            int k = kbase + kk;
            ulonglong2 wv[4], hv[4];
#pragma unroll
            for (int i = 0; i < 4; i++)
                wv[i] = *(const ulonglong2*)(wh_s + (rowpos * 4 + i) * 516 + k);
#pragma unroll
            for (int j = 0; j < 4; j++)
                hv[j] = *(const ulonglong2*)(h_s + (j * 16 + bpos) * 516 + k);
#pragma unroll
            for (int i = 0; i < 4; i++)
#pragma unroll
                for (int j = 0; j < 4; j++) {
                    FMA2(acc[i][j], wv[i].x, hv[j].x);
                    FMA2(acc[i][j], wv[i].y, hv[j].y);
                }
        }
        CP_WAIT(0);
        NBAR(1 + grp, 64);
#pragma unroll 4
        for (int kk = 64; kk < 128; kk += 4) {
            int k = kbase + kk;
            ulonglong2 wv[4], hv[4];
#pragma unroll
            for (int i = 0; i < 4; i++)
                wv[i] = *(const ulonglong2*)(wh_s + (rowpos * 4 + i) * 516 + k);
#pragma unroll
            for (int j = 0; j < 4; j++)
                hv[j] = *(const ulonglong2*)(h_s + (j * 16 + bpos) * 516 + k);
#pragma unroll
            for (int i = 0; i < 4; i++)
#pragma unroll
                for (int j = 0; j < 4; j++) {
                    FMA2(acc[i][j], wv[i].x, hv[j].x);
                    FMA2(acc[i][j], wv[i].y, hv[j].y);
                }
        }

        // write partials: part[grp][rowpos*4+i][j*16+bpos]
#pragma unroll
        for (int i = 0; i < 4; i++)
#pragma unroll
            for (int j = 0; j < 4; j++) {
                float lo, hi;
                unpack2(acc[i][j], lo, hi);
                part[grp * 1088 + (rowpos * 4 + i) * 68 + (j * 16 + bpos)] = lo + hi;
            }
        __syncthreads();

        // elementwise: this thread owns (batch eb, hidden jglob)
        float gate0 = bi0 + xv0, gate1 = bi1 + xv1, gate2 = bi2 + xv2, gate3 = bi3 + xv3;
#pragma unroll
        for (int gr2 = 0; gr2 < 4; gr2++) {
            const float* p = part + gr2 * 1088;
            gate0 += p[(0 * 4 + ejl) * 68 + eb];
            gate1 += p[(1 * 4 + ejl) * 68 + eb];
            gate2 += p[(2 * 4 + ejl) * 68 + eb];
            gate3 += p[(3 * 4 + ejl) * 68 + eb];
        }
        float ig = sigf(gate0);
        float fg = sigf(gate1);
        float gg = tanhf(gate2);
        float og = sigf(gate3);
        creg = fg * creg + ig * gg;
        float hnew = og * tanhf(creg);

        if (t == S_ - 1) {
            out[((size_t)eb * S_ + t) * H_ + jglob] = hnew;
            out[(size_t)B_ * S_ * H_ + eb * H_ + jglob] = hnew;                 // final h
            out[(size_t)B_ * S_ * H_ + B_ * H_ + eb * H_ + jglob] = creg;       // final c
        } else {
            g_h[t & 1][eb * H_ + jglob] = hnew;
            __syncthreads();   // all h stores of this CTA issued
            // release: st.release orders the prior weak h-stores at gpu scope
            if (tid == 0) {
                unsigned tgt = base + (unsigned)t + 1u;
                asm volatile("st.global.release.gpu.b32 [%0], %1;"
                             :: "l"(g_flags + g), "r"(tgt) : "memory");
            }
            // out store off the critical path, after the release
            out[((size_t)eb * S_ + t) * H_ + jglob] = hnew;
        }
    }
}

// ---------------- launch ----------------
extern "C" void kernel_launch(void* const* d_in, const int* in_sizes, int n_in,
                              void* d_out, int out_size) {
    (void)in_sizes; (void)n_in; (void)out_size;
    const float* x  = (const float*)d_in[0];
    const float* W  = (const float*)d_in[1];
    const float* bb = (const float*)d_in[2];
    const float* h0 = (const float*)d_in[3];
    const float* c0 = (const float*)d_in[4];
    float* out = (float*)d_out;

    repack_kernel<<<(R4H_ * KTOT + 255) / 256, 256>>>(W);

    cudaFuncSetAttribute(xproj_kernel, cudaFuncAttributeMaxDynamicSharedMemorySize, XP_SMEM);
    xproj_kernel<<<dim3(16, S_), 256, XP_SMEM>>>(x);

    cudaFuncSetAttribute(lstm_step_kernel, cudaFuncAttributeMaxDynamicSharedMemorySize, ST_SMEM);
    lstm_step_kernel<<<128, 256, ST_SMEM>>>(h0, c0, bb, out);
}